// round 4
// baseline (speedup 1.0000x reference)
#include <cuda_runtime.h>
#include <cuda_fp16.h>
#include <cstdint>

#define EPSILON_F 1e-9f
#define NQ 100
#define L_SEQ 512

__device__ float g_base;

__global__ void scalar_kernel(const float* __restrict__ t_ptr) {
    const float t = *t_ptr;
    const int i = threadIdx.x;           // 128 threads
    float val = 0.0f;
    if (i < NQ - 1) {
        float Ei = ((float)i       * (1.0f / (NQ - 1))) * t;
        float Ej = ((float)(i + 1) * (1.0f / (NQ - 1))) * t;
        val = 0.5f * (expf(-Ei) + expf(-Ej)) * (Ej - Ei);
    }
    #pragma unroll
    for (int off = 16; off; off >>= 1)
        val += __shfl_xor_sync(0xffffffffu, val, off);
    __shared__ float ws[4];
    if ((threadIdx.x & 31) == 0) ws[threadIdx.x >> 5] = val;
    __syncthreads();
    if (threadIdx.x == 0) {
        float drag = ws[0] + ws[1] + ws[2] + ws[3];
        float scattering = -0.5f * t * logf(t + EPSILON_F);
        g_base = scattering + drag;
    }
}

// Persistent: 1 CTA/SM, fp16 table in smem. 2 rows per warp-iteration:
// 8 front-batched LDG.128 (32KB in flight/SM) to hide DRAM latency,
// gathers via LDS crossbar, 2 accumulators per row.
__global__ __launch_bounds__(1024, 1)
void gather_kernel(const int* __restrict__ idx,
                   const float* __restrict__ eta,
                   float* __restrict__ out, int B, int V) {
    extern __shared__ __half sh[];
    const int tid = threadIdx.x;

    // stage table: fp32 -> fp16 smem (vectorized)
    const int nv4 = V >> 2;
    const float4* e4 = reinterpret_cast<const float4*>(eta);
    for (int i = tid; i < nv4; i += blockDim.x) {
        float4 v = __ldg(e4 + i);
        __half2* dst = reinterpret_cast<__half2*>(sh + 4 * i);
        dst[0] = __floats2half2_rn(v.x, v.y);
        dst[1] = __floats2half2_rn(v.z, v.w);
    }
    for (int i = (nv4 << 2) + tid; i < V; i += blockDim.x)
        sh[i] = __float2half_rn(__ldg(eta + i));
    __syncthreads();

    const float base  = g_base;
    const int warp    = tid >> 5;
    const int lane    = tid & 31;
    const int warps   = blockDim.x >> 5;          // 32 warps
    const int stride  = gridDim.x * warps;        // in row-pairs
    const int npairs  = (B + 1) >> 1;

    for (int pair = blockIdx.x * warps + warp; pair < npairs; pair += stride) {
        const int r0 = pair << 1;
        const int r1 = r0 + 1;
        const bool has1 = (r1 < B);

        const int4* p0 = reinterpret_cast<const int4*>(idx + (size_t)r0 * L_SEQ);
        const int4* p1 = reinterpret_cast<const int4*>(idx + (size_t)r1 * L_SEQ);

        // front-batch 8 LDG.128 (2 rows) — streaming, keep caches for eta
        int4 u0[4], u1[4];
        #pragma unroll
        for (int j = 0; j < 4; j++) u0[j] = __ldcs(&p0[j * 32 + lane]);
        if (has1) {
            #pragma unroll
            for (int j = 0; j < 4; j++) u1[j] = __ldcs(&p1[j * 32 + lane]);
        }

        // row 0 gathers, 2 accumulators
        float a0 = 0.0f, b0 = 0.0f;
        #pragma unroll
        for (int j = 0; j < 4; j++) {
            a0 += __half2float(sh[u0[j].x]);
            b0 += __half2float(sh[u0[j].y]);
            a0 += __half2float(sh[u0[j].z]);
            b0 += __half2float(sh[u0[j].w]);
        }
        float s0 = a0 + b0;

        float s1 = 0.0f;
        if (has1) {
            float a1 = 0.0f, b1 = 0.0f;
            #pragma unroll
            for (int j = 0; j < 4; j++) {
                a1 += __half2float(sh[u1[j].x]);
                b1 += __half2float(sh[u1[j].y]);
                a1 += __half2float(sh[u1[j].z]);
                b1 += __half2float(sh[u1[j].w]);
            }
            s1 = a1 + b1;
        }

        #pragma unroll
        for (int off = 16; off; off >>= 1) {
            s0 += __shfl_xor_sync(0xffffffffu, s0, off);
            s1 += __shfl_xor_sync(0xffffffffu, s1, off);
        }

        if (lane == 0) {
            out[r0] = s0 + base;
            if (has1) out[r1] = s1 + base;
        }
    }
}

extern "C" void kernel_launch(void* const* d_in, const int* in_sizes, int n_in,
                              void* d_out, int out_size) {
    const int*   idx = (const int*)d_in[0];     // [B, 512] int32
    const float* eta = (const float*)d_in[1];   // [V] f32
    const float* t   = (const float*)d_in[2];   // scalar f32
    float* out = (float*)d_out;

    const int B = in_sizes[0] / L_SEQ;
    const int V = in_sizes[1];

    scalar_kernel<<<1, 128>>>(t);

    int dev = 0, sms = 148;
    cudaGetDevice(&dev);
    cudaDeviceGetAttribute(&sms, cudaDevAttrMultiProcessorCount, dev);

    size_t smem = (size_t)V * sizeof(__half);   // 200,000 B for V=100000
    cudaFuncSetAttribute(gather_kernel,
                         cudaFuncAttributeMaxDynamicSharedMemorySize, (int)smem);

    gather_kernel<<<sms, 1024, smem>>>(idx, eta, out, B, V);
}

// round 5
// speedup vs baseline: 1.1603x; 1.1603x over previous
#include <cuda_runtime.h>
#include <cuda_fp16.h>
#include <cstdint>

#define EPSILON_F 1e-9f
#define NQ 100
#define L_SEQ 512

__device__ float g_base;

__global__ void scalar_kernel(const float* __restrict__ t_ptr) {
    const float t = *t_ptr;
    const int i = threadIdx.x;           // 128 threads
    float val = 0.0f;
    if (i < NQ - 1) {
        float Ei = ((float)i       * (1.0f / (NQ - 1))) * t;
        float Ej = ((float)(i + 1) * (1.0f / (NQ - 1))) * t;
        val = 0.5f * (expf(-Ei) + expf(-Ej)) * (Ej - Ei);
    }
    #pragma unroll
    for (int off = 16; off; off >>= 1)
        val += __shfl_xor_sync(0xffffffffu, val, off);
    __shared__ float ws[4];
    if ((threadIdx.x & 31) == 0) ws[threadIdx.x >> 5] = val;
    __syncthreads();
    if (threadIdx.x == 0) {
        float drag = ws[0] + ws[1] + ws[2] + ws[3];
        float scattering = -0.5f * t * logf(t + EPSILON_F);
        g_base = scattering + drag;
    }
}

// Persistent: 1 CTA/SM, fp16 table in smem.
// Software pipeline: prefetch next row's 4x LDG.128 into registers BEFORE
// consuming the current row, so DRAM latency overlaps gather+reduce work.
__global__ __launch_bounds__(1024, 1)
void gather_kernel(const int* __restrict__ idx,
                   const float* __restrict__ eta,
                   float* __restrict__ out, int B, int V) {
    extern __shared__ __half sh[];
    const int tid = threadIdx.x;

    // stage table: fp32 -> fp16 smem (vectorized)
    const int nv4 = V >> 2;
    const float4* e4 = reinterpret_cast<const float4*>(eta);
    for (int i = tid; i < nv4; i += blockDim.x) {
        float4 v = __ldg(e4 + i);
        __half2* dst = reinterpret_cast<__half2*>(sh + 4 * i);
        dst[0] = __floats2half2_rn(v.x, v.y);
        dst[1] = __floats2half2_rn(v.z, v.w);
    }
    for (int i = (nv4 << 2) + tid; i < V; i += blockDim.x)
        sh[i] = __float2half_rn(__ldg(eta + i));
    __syncthreads();

    const float base  = g_base;
    const int warp    = tid >> 5;
    const int lane    = tid & 31;
    const int warps   = blockDim.x >> 5;          // 32 warps
    const int stride  = gridDim.x * warps;

    int row = blockIdx.x * warps + warp;
    if (row >= B) return;

    // prologue: load first row's indices
    int4 cur[4];
    {
        const int4* p = reinterpret_cast<const int4*>(idx + (size_t)row * L_SEQ);
        #pragma unroll
        for (int j = 0; j < 4; j++) cur[j] = __ldcs(&p[j * 32 + lane]);
    }

    for (; row < B; row += stride) {
        const int nrow = row + stride;

        // prefetch next row's indices (independent of current gathers)
        int4 nxt[4];
        if (nrow < B) {
            const int4* p = reinterpret_cast<const int4*>(idx + (size_t)nrow * L_SEQ);
            #pragma unroll
            for (int j = 0; j < 4; j++) nxt[j] = __ldcs(&p[j * 32 + lane]);
        }

        // gather current row from smem (2 accumulators)
        float a = 0.0f, b = 0.0f;
        #pragma unroll
        for (int j = 0; j < 4; j++) {
            a += __half2float(sh[cur[j].x]);
            b += __half2float(sh[cur[j].y]);
            a += __half2float(sh[cur[j].z]);
            b += __half2float(sh[cur[j].w]);
        }
        float s = a + b;

        #pragma unroll
        for (int off = 16; off; off >>= 1)
            s += __shfl_xor_sync(0xffffffffu, s, off);

        if (lane == 0) out[row] = s + base;

        #pragma unroll
        for (int j = 0; j < 4; j++) cur[j] = nxt[j];
    }
}

extern "C" void kernel_launch(void* const* d_in, const int* in_sizes, int n_in,
                              void* d_out, int out_size) {
    const int*   idx = (const int*)d_in[0];     // [B, 512] int32
    const float* eta = (const float*)d_in[1];   // [V] f32
    const float* t   = (const float*)d_in[2];   // scalar f32
    float* out = (float*)d_out;

    const int B = in_sizes[0] / L_SEQ;
    const int V = in_sizes[1];

    scalar_kernel<<<1, 128>>>(t);

    int dev = 0, sms = 148;
    cudaGetDevice(&dev);
    cudaDeviceGetAttribute(&sms, cudaDevAttrMultiProcessorCount, dev);

    size_t smem = (size_t)V * sizeof(__half);   // 200,000 B for V=100000
    cudaFuncSetAttribute(gather_kernel,
                         cudaFuncAttributeMaxDynamicSharedMemorySize, (int)smem);

    gather_kernel<<<sms, 1024, smem>>>(idx, eta, out, B, V);
}